// round 1
// baseline (speedup 1.0000x reference)
#include <cuda_runtime.h>
#include <cstdint>

// Problem constants (fixed by the dataset)
#define ENTRY_SIZE 8192
#define TUPLE_SIZE 16
#define N_NEURONS  512      // ENTRY_SIZE / TUPLE_SIZE
#define ADDR_BITS  16
#define BATCH      4096

// Scratch: normalized int32 tuple mapping + identity flag.
__device__ int g_map[ENTRY_SIZE];
__device__ int g_identity;

// ---------------------------------------------------------------------------
// Prep kernels: normalize tuple_mapping (which may arrive as int32 or int64
// depending on the reference's jax x64 config) into g_map, and detect whether
// it is the identity permutation (it is, for this dataset) so the main kernel
// can take a vectorized fast path.
// ---------------------------------------------------------------------------
__global__ void prep_init_kernel() {
    g_identity = 1;
}

__global__ void prep_map_kernel(const void* __restrict__ map_raw, int n) {
    // dtype probe: element [1] read as int64.
    //   int64 identity layout -> value 1 (any valid mapping value < ENTRY_SIZE)
    //   int32 layout reinterpreted -> (m32[2] | m32[3]<<32), huge for arange.
    const long long* m64 = (const long long*)map_raw;
    const int*       m32 = (const int*)map_raw;
    long long probe = m64[1];
    bool is64 = (probe >= 0 && probe < (long long)ENTRY_SIZE);

    int i = blockIdx.x * blockDim.x + threadIdx.x;
    if (i < n) {
        int v = is64 ? (int)m64[i] : m32[i];
        g_map[i] = v;
        if (v != i) atomicExch(&g_identity, 0);
    }
}

// ---------------------------------------------------------------------------
// Main kernel: one block per sample, one thread per neuron.
//   addr(b,n) = sum_t input[b, map[n*16+t]] << (15 - t)
//   c = counts[n, addr]; s = sums[n, addr]
//   out[b] = (sum_{c>0} s) / (sum_{c>0} c), 0 if denominator is 0.
// ---------------------------------------------------------------------------
__global__ __launch_bounds__(N_NEURONS)
void wisard_kernel(const int*   __restrict__ input,
                   const int*   __restrict__ counts,
                   const float* __restrict__ sums,
                   float*       __restrict__ out) {
    const int b = blockIdx.x;
    const int n = threadIdx.x;

    int addr = 0;
    if (g_identity) {
        // Fast path: neuron n owns 16 consecutive bits -> 4x int4 loads.
        const int4* p = (const int4*)(input + (size_t)b * ENTRY_SIZE) + n * 4;
#pragma unroll
        for (int i = 0; i < 4; i++) {
            int4 v = __ldg(p + i);
            // element t=4i has weight bit (15-4i): first group lands in the
            // top nibble after the 4 shifts.
            addr = (addr << 4) | ((v.x & 1) << 3) | ((v.y & 1) << 2)
                               | ((v.z & 1) << 1) |  (v.w & 1);
        }
    } else {
        // Generic path: honor arbitrary permutation (scalar gathers; the
        // mapping table is tiny and cache-hot).
        const int* base = input + (size_t)b * ENTRY_SIZE;
#pragma unroll
        for (int t = 0; t < TUPLE_SIZE; t++) {
            int bit = base[g_map[n * TUPLE_SIZE + t]] & 1;
            addr |= bit << (TUPLE_SIZE - 1 - t);
        }
    }

    const size_t idx = ((size_t)n << ADDR_BITS) | (unsigned)addr;
    const int   c = __ldg(counts + idx);
    const float s = __ldg(sums + idx);

    float rs = (c > 0) ? s : 0.0f;
    int   rc = (c > 0) ? c : 0;

    // Warp reduction.
#pragma unroll
    for (int o = 16; o > 0; o >>= 1) {
        rs += __shfl_xor_sync(0xFFFFFFFFu, rs, o);
        rc += __shfl_xor_sync(0xFFFFFFFFu, rc, o);
    }

    __shared__ float s_sum[N_NEURONS / 32];
    __shared__ int   s_cnt[N_NEURONS / 32];
    const int w = n >> 5;
    const int l = n & 31;
    if (l == 0) { s_sum[w] = rs; s_cnt[w] = rc; }
    __syncthreads();

    if (w == 0) {
        float r  = (l < N_NEURONS / 32) ? s_sum[l] : 0.0f;
        int   c2 = (l < N_NEURONS / 32) ? s_cnt[l] : 0;
#pragma unroll
        for (int o = 8; o > 0; o >>= 1) {
            r  += __shfl_xor_sync(0xFFFFFFFFu, r, o);
            c2 += __shfl_xor_sync(0xFFFFFFFFu, c2, o);
        }
        if (l == 0) {
            // counters == 0 implies response == 0 too -> nan_to_num(0/0) = 0
            out[b] = (c2 > 0) ? (r / (float)c2) : 0.0f;
        }
    }
}

extern "C" void kernel_launch(void* const* d_in, const int* in_sizes, int n_in,
                              void* d_out, int out_size) {
    const int*   input   = (const int*)d_in[0];
    const void*  mapping = d_in[1];              // int32 or int64 (detected)
    const int*   counts  = (const int*)d_in[2];
    const float* sums    = (const float*)d_in[3];
    float*       out     = (float*)d_out;

    prep_init_kernel<<<1, 1>>>();
    prep_map_kernel<<<(ENTRY_SIZE + 255) / 256, 256>>>(mapping, ENTRY_SIZE);
    wisard_kernel<<<BATCH, N_NEURONS>>>(input, counts, sums, out);
}

// round 2
// speedup vs baseline: 1.0316x; 1.0316x over previous
#include <cuda_runtime.h>
#include <cstdint>

// Problem constants (fixed by the dataset)
#define ENTRY_SIZE 8192
#define TUPLE_SIZE 16
#define N_NEURONS  512      // ENTRY_SIZE / TUPLE_SIZE
#define ADDR_BITS  16
#define BATCH      4096
#define SPB        2        // samples per block

// Scratch: normalized int32 tuple mapping + identity flag.
__device__ int g_map[ENTRY_SIZE];
__device__ int g_identity;

// ---------------------------------------------------------------------------
// Single prep kernel (one block): normalize tuple_mapping (int32 or int64 —
// detected by a probe) into g_map and set g_identity. One kernel so the
// per-call launch sequence is [prep, main] and ncu's -s 5 -c 1 lands on main.
// ---------------------------------------------------------------------------
__global__ void prep_kernel(const void* __restrict__ map_raw) {
    __shared__ int flag;
    if (threadIdx.x == 0) flag = 1;
    __syncthreads();

    const long long* m64 = (const long long*)map_raw;
    const int*       m32 = (const int*)map_raw;
    // dtype probe: element [1] as int64. int64 identity -> small value;
    // int32 layout reinterpreted -> (m32[2] | m32[3]<<32), huge for arange.
    long long probe = m64[1];
    bool is64 = (probe >= 0 && probe < (long long)ENTRY_SIZE);

    bool ok = true;
    for (int i = threadIdx.x; i < ENTRY_SIZE; i += blockDim.x) {
        int v = is64 ? (int)m64[i] : m32[i];
        g_map[i] = v;
        if (v != i) ok = false;
    }
    if (!ok) atomicExch(&flag, 0);
    __syncthreads();
    if (threadIdx.x == 0) g_identity = flag;
}

// ---------------------------------------------------------------------------
// Main kernel: one block per SPB samples, one thread per neuron.
//   addr(b,n) = sum_t input[b, map[n*16+t]] << (15 - t)
//   c = counts[n, addr]; s = sums[n, addr]
//   out[b] = (sum_{c>0} s) / (sum_{c>0} c), 0 if denominator is 0.
// Cache policy: input is stream-once -> __ldcs (evict-first, keeps L2 for the
// tables). Gathers are random 4B with no L1 reuse -> __ldcg (L2 only), so the
// ~1.27x per-sector reuse can be captured in L2.
// ---------------------------------------------------------------------------
__global__ __launch_bounds__(N_NEURONS, 2)
void wisard_kernel(const int*   __restrict__ input,
                   const int*   __restrict__ counts,
                   const float* __restrict__ sums,
                   float*       __restrict__ out) {
    const int b0 = blockIdx.x * SPB;
    const int n  = threadIdx.x;

    unsigned addr[SPB];
    const bool ident = (g_identity != 0);

#pragma unroll
    for (int s = 0; s < SPB; s++) {
        unsigned a = 0;
        if (ident) {
            // Fast path: neuron n owns 16 consecutive bits -> 4x int4 loads.
            const int4* p = (const int4*)(input + (size_t)(b0 + s) * ENTRY_SIZE) + n * 4;
#pragma unroll
            for (int i = 0; i < 4; i++) {
                int4 v = __ldcs(p + i);
                a = (a << 4) | ((v.x & 1) << 3) | ((v.y & 1) << 2)
                             | ((v.z & 1) << 1) |  (v.w & 1);
            }
        } else {
            // Generic path: honor arbitrary permutation (map is tiny & cache-hot).
            const int* base = input + (size_t)(b0 + s) * ENTRY_SIZE;
#pragma unroll
            for (int t = 0; t < TUPLE_SIZE; t++) {
                int bit = base[g_map[n * TUPLE_SIZE + t]] & 1;
                a |= (unsigned)bit << (TUPLE_SIZE - 1 - t);
            }
        }
        addr[s] = a;
    }

    // Issue all gathers back-to-back for maximum MLP.
    int   c[SPB];
    float sv[SPB];
#pragma unroll
    for (int s = 0; s < SPB; s++) {
        const size_t idx = ((size_t)n << ADDR_BITS) | addr[s];
        c[s]  = __ldcg(counts + idx);
        sv[s] = __ldcg(sums + idx);
    }

    float rs[SPB];
    int   rc[SPB];
#pragma unroll
    for (int s = 0; s < SPB; s++) {
        rs[s] = (c[s] > 0) ? sv[s] : 0.0f;
        rc[s] = (c[s] > 0) ? c[s]  : 0;
    }

    // Warp reduction (both samples together).
#pragma unroll
    for (int o = 16; o > 0; o >>= 1) {
#pragma unroll
        for (int s = 0; s < SPB; s++) {
            rs[s] += __shfl_xor_sync(0xFFFFFFFFu, rs[s], o);
            rc[s] += __shfl_xor_sync(0xFFFFFFFFu, rc[s], o);
        }
    }

    __shared__ float s_sum[SPB][N_NEURONS / 32];
    __shared__ int   s_cnt[SPB][N_NEURONS / 32];
    const int w = n >> 5;
    const int l = n & 31;
    if (l == 0) {
#pragma unroll
        for (int s = 0; s < SPB; s++) { s_sum[s][w] = rs[s]; s_cnt[s][w] = rc[s]; }
    }
    __syncthreads();

    // Warp s finalizes sample s.
    if (w < SPB) {
        float r  = (l < N_NEURONS / 32) ? s_sum[w][l] : 0.0f;
        int   c2 = (l < N_NEURONS / 32) ? s_cnt[w][l] : 0;
#pragma unroll
        for (int o = 8; o > 0; o >>= 1) {
            r  += __shfl_xor_sync(0xFFFFFFFFu, r, o);
            c2 += __shfl_xor_sync(0xFFFFFFFFu, c2, o);
        }
        if (l == 0) {
            // counters == 0 implies response == 0 too -> nan_to_num(0/0) = 0
            out[b0 + w] = (c2 > 0) ? (r / (float)c2) : 0.0f;
        }
    }
}

extern "C" void kernel_launch(void* const* d_in, const int* in_sizes, int n_in,
                              void* d_out, int out_size) {
    const int*   input   = (const int*)d_in[0];
    const void*  mapping = d_in[1];              // int32 or int64 (detected)
    const int*   counts  = (const int*)d_in[2];
    const float* sums    = (const float*)d_in[3];
    float*       out     = (float*)d_out;

    prep_kernel<<<1, N_NEURONS>>>(mapping);
    wisard_kernel<<<BATCH / SPB, N_NEURONS>>>(input, counts, sums, out);
}

// round 4
// speedup vs baseline: 1.1145x; 1.0803x over previous
#include <cuda_runtime.h>
#include <cstdint>

// Problem constants (fixed by the dataset)
#define ENTRY_SIZE 8192
#define TUPLE_SIZE 16
#define N_NEURONS  512      // ENTRY_SIZE / TUPLE_SIZE
#define ADDR_BITS  16
#define BATCH      4096
#define SPB        2        // samples per block

// Scratch: normalized int32 tuple mapping + identity flag.
__device__ int g_map[ENTRY_SIZE];
__device__ int g_identity;

// ---------------------------------------------------------------------------
// L2-eviction-steered loads via createpolicy + L2::cache_hint (the direct
// .L2::evict_* ld modifier is rejected by ptxas on sm_103a for <256-bit).
//  - Tables (counts/sums): evict_last -> sticky in L2. L2 persists across
//    graph replays, so a large slice of the 256MB tables stays resident.
//  - Input: evict_first -> the 128MB stream doesn't flush the tables.
// ---------------------------------------------------------------------------
__device__ __forceinline__ unsigned long long mk_policy_last() {
    unsigned long long p;
    asm("createpolicy.fractional.L2::evict_last.b64 %0, 1.0;" : "=l"(p));
    return p;
}
__device__ __forceinline__ unsigned long long mk_policy_first() {
    unsigned long long p;
    asm("createpolicy.fractional.L2::evict_first.b64 %0, 1.0;" : "=l"(p));
    return p;
}
__device__ __forceinline__ int ld_hint_i32(const int* p, unsigned long long pol) {
    int v;
    asm("ld.global.nc.L2::cache_hint.b32 %0, [%1], %2;" : "=r"(v) : "l"(p), "l"(pol));
    return v;
}
__device__ __forceinline__ float ld_hint_f32(const float* p, unsigned long long pol) {
    float v;
    asm("ld.global.nc.L2::cache_hint.f32 %0, [%1], %2;" : "=f"(v) : "l"(p), "l"(pol));
    return v;
}
__device__ __forceinline__ int4 ld_hint_i4(const int4* p, unsigned long long pol) {
    int4 v;
    asm("ld.global.nc.L2::cache_hint.v4.b32 {%0,%1,%2,%3}, [%4], %5;"
        : "=r"(v.x), "=r"(v.y), "=r"(v.z), "=r"(v.w) : "l"(p), "l"(pol));
    return v;
}

// ---------------------------------------------------------------------------
// Single prep kernel (one block): normalize tuple_mapping (int32 or int64 —
// detected by a probe) into g_map and set g_identity.
// ---------------------------------------------------------------------------
__global__ void prep_kernel(const void* __restrict__ map_raw) {
    __shared__ int flag;
    if (threadIdx.x == 0) flag = 1;
    __syncthreads();

    const long long* m64 = (const long long*)map_raw;
    const int*       m32 = (const int*)map_raw;
    // dtype probe: element [1] as int64. int64 identity -> small value;
    // int32 layout reinterpreted -> huge for arange.
    long long probe = m64[1];
    bool is64 = (probe >= 0 && probe < (long long)ENTRY_SIZE);

    bool ok = true;
    for (int i = threadIdx.x; i < ENTRY_SIZE; i += blockDim.x) {
        int v = is64 ? (int)m64[i] : m32[i];
        g_map[i] = v;
        if (v != i) ok = false;
    }
    if (!ok) atomicExch(&flag, 0);
    __syncthreads();
    if (threadIdx.x == 0) g_identity = flag;
}

// ---------------------------------------------------------------------------
// Main kernel: one block per SPB samples, one thread per neuron.
//   addr(b,n) = sum_t input[b, map[n*16+t]] << (15 - t)
//   c = counts[n, addr]; s = sums[n, addr]  (s only loaded when c > 0)
//   out[b] = (sum_{c>0} s) / (sum_{c>0} c), 0 if denominator is 0.
// ---------------------------------------------------------------------------
__global__ __launch_bounds__(N_NEURONS, 2)
void wisard_kernel(const int*   __restrict__ input,
                   const int*   __restrict__ counts,
                   const float* __restrict__ sums,
                   float*       __restrict__ out) {
    const int b0 = blockIdx.x * SPB;
    const int n  = threadIdx.x;

    const unsigned long long pol_last  = mk_policy_last();
    const unsigned long long pol_first = mk_policy_first();

    unsigned addr[SPB];
    const bool ident = (g_identity != 0);

#pragma unroll
    for (int s = 0; s < SPB; s++) {
        unsigned a = 0;
        if (ident) {
            // Fast path: neuron n owns 16 consecutive bits -> 4x int4 loads.
            const int4* p = (const int4*)(input + (size_t)(b0 + s) * ENTRY_SIZE) + n * 4;
#pragma unroll
            for (int i = 0; i < 4; i++) {
                int4 v = ld_hint_i4(p + i, pol_first);
                a = (a << 4) | ((v.x & 1) << 3) | ((v.y & 1) << 2)
                             | ((v.z & 1) << 1) |  (v.w & 1);
            }
        } else {
            // Generic path: honor arbitrary permutation (map is tiny & cache-hot).
            const int* base = input + (size_t)(b0 + s) * ENTRY_SIZE;
#pragma unroll
            for (int t = 0; t < TUPLE_SIZE; t++) {
                int bit = base[g_map[n * TUPLE_SIZE + t]] & 1;
                a |= (unsigned)bit << (TUPLE_SIZE - 1 - t);
            }
        }
        addr[s] = a;
    }

    // Counts gathers first (max MLP), then sums gathers predicated on c>0
    // (~25% of counts are 0 -> skip those sums sectors entirely).
    int c[SPB];
#pragma unroll
    for (int s = 0; s < SPB; s++) {
        const size_t idx = ((size_t)n << ADDR_BITS) | addr[s];
        c[s] = ld_hint_i32(counts + idx, pol_last);
    }

    float rs[SPB];
    int   rc[SPB];
#pragma unroll
    for (int s = 0; s < SPB; s++) {
        const size_t idx = ((size_t)n << ADDR_BITS) | addr[s];
        bool t = (c[s] > 0);
        rs[s] = t ? ld_hint_f32(sums + idx, pol_last) : 0.0f;
        rc[s] = t ? c[s] : 0;
    }

    // Warp reduction (both samples together).
#pragma unroll
    for (int o = 16; o > 0; o >>= 1) {
#pragma unroll
        for (int s = 0; s < SPB; s++) {
            rs[s] += __shfl_xor_sync(0xFFFFFFFFu, rs[s], o);
            rc[s] += __shfl_xor_sync(0xFFFFFFFFu, rc[s], o);
        }
    }

    __shared__ float s_sum[SPB][N_NEURONS / 32];
    __shared__ int   s_cnt[SPB][N_NEURONS / 32];
    const int w = n >> 5;
    const int l = n & 31;
    if (l == 0) {
#pragma unroll
        for (int s = 0; s < SPB; s++) { s_sum[s][w] = rs[s]; s_cnt[s][w] = rc[s]; }
    }
    __syncthreads();

    // Warp s finalizes sample s.
    if (w < SPB) {
        float r  = (l < N_NEURONS / 32) ? s_sum[w][l] : 0.0f;
        int   c2 = (l < N_NEURONS / 32) ? s_cnt[w][l] : 0;
#pragma unroll
        for (int o = 8; o > 0; o >>= 1) {
            r  += __shfl_xor_sync(0xFFFFFFFFu, r, o);
            c2 += __shfl_xor_sync(0xFFFFFFFFu, c2, o);
        }
        if (l == 0) {
            // counters == 0 implies response == 0 too -> nan_to_num(0/0) = 0
            out[b0 + w] = (c2 > 0) ? (r / (float)c2) : 0.0f;
        }
    }
}

extern "C" void kernel_launch(void* const* d_in, const int* in_sizes, int n_in,
                              void* d_out, int out_size) {
    const int*   input   = (const int*)d_in[0];
    const void*  mapping = d_in[1];              // int32 or int64 (detected)
    const int*   counts  = (const int*)d_in[2];
    const float* sums    = (const float*)d_in[3];
    float*       out     = (float*)d_out;

    prep_kernel<<<1, N_NEURONS>>>(mapping);
    wisard_kernel<<<BATCH / SPB, N_NEURONS>>>(input, counts, sums, out);
}